// round 2
// baseline (speedup 1.0000x reference)
#include <cuda_runtime.h>

#define LL   2048
#define BB   2
#define DMODEL 512
#define HH   8
#define DKK  64
#define NT   4096   // BB*LL
#define HB   16     // HH*BB

// ---------------- scratch (device globals; no allocation allowed) ----------------
__device__ float g_qh[HB * LL * DKK];   // [h*2+b][l][d], pre-scaled by 1/64
__device__ float g_kh[HB * LL * DKK];
__device__ float g_vh[HB * LL * DKK];
__device__ float g_ctx[NT * DMODEL];    // [b*L+l][h*64+d]
__device__ float g_m[HB * LL];          // row max
__device__ float g_linv[HB * LL];       // 1 / row sumexp

// =====================================================================
// Kernel 1: fused QKV projection.  Y = (X @ W + b) [* 1/64 for Q]
// X: [4096,512] row-major.  Tile 128x128x16, 256 threads, 8x8 microtile.
// =====================================================================
__global__ __launch_bounds__(256) void proj_kernel(
    const float* __restrict__ qin, const float* __restrict__ kin, const float* __restrict__ vin,
    const float* __restrict__ Wq, const float* __restrict__ bq,
    const float* __restrict__ Wk, const float* __restrict__ bk,
    const float* __restrict__ Wv, const float* __restrict__ bv)
{
    __shared__ float As[16][128];   // [k][row]
    __shared__ float Bs[16][128];   // [k][col]

    const int z = blockIdx.z;
    const float* X    = (z == 0) ? qin : (z == 1) ? kin : vin;
    const float* W    = (z == 0) ? Wq  : (z == 1) ? Wk  : Wv;
    const float* bias = (z == 0) ? bq  : (z == 1) ? bk  : bv;
    float* outp       = (z == 0) ? g_qh : (z == 1) ? g_kh : g_vh;
    const float scale = (z == 0) ? (1.0f / 64.0f) : 1.0f;

    const int col0 = blockIdx.x * 128;
    const int row0 = blockIdx.y * 128;
    const int t = threadIdx.x, tx = t & 15, ty = t >> 4;

    float acc[8][8];
#pragma unroll
    for (int i = 0; i < 8; i++)
#pragma unroll
        for (int j = 0; j < 8; j++) acc[i][j] = 0.0f;

    for (int k0 = 0; k0 < DMODEL; k0 += 16) {
#pragma unroll
        for (int p = 0; p < 2; p++) {
            int fi = t + p * 256;
            // A tile: 128 rows x 16 k  (transpose into As[k][row])
            int k4 = fi & 3, row = fi >> 2;
            float4 fa = *(const float4*)(X + (size_t)(row0 + row) * DMODEL + k0 + k4 * 4);
            As[k4 * 4 + 0][row] = fa.x; As[k4 * 4 + 1][row] = fa.y;
            As[k4 * 4 + 2][row] = fa.z; As[k4 * 4 + 3][row] = fa.w;
            // B tile: 16 k x 128 cols
            int c4 = fi & 31, kk = fi >> 5;
            float4 fb = *(const float4*)(W + (size_t)(k0 + kk) * DMODEL + col0 + c4 * 4);
            *(float4*)&Bs[kk][c4 * 4] = fb;
        }
        __syncthreads();
#pragma unroll
        for (int kk = 0; kk < 16; kk++) {
            float a[8], bf[8];
            *(float4*)&a[0]  = *(float4*)&As[kk][ty * 4];
            *(float4*)&a[4]  = *(float4*)&As[kk][64 + ty * 4];
            *(float4*)&bf[0] = *(float4*)&Bs[kk][tx * 4];
            *(float4*)&bf[4] = *(float4*)&Bs[kk][64 + tx * 4];
#pragma unroll
            for (int i = 0; i < 8; i++)
#pragma unroll
                for (int j = 0; j < 8; j++) acc[i][j] += a[i] * bf[j];
        }
        __syncthreads();
    }

    // epilogue: scatter into [h][b][l][d] layout
#pragma unroll
    for (int i = 0; i < 8; i++) {
        int row = row0 + ((i < 4) ? ty * 4 + i : 64 + ty * 4 + (i - 4));
        int bidx = row >> 11, l = row & 2047;
#pragma unroll
        for (int jj = 0; jj < 2; jj++) {
            int colb = col0 + (jj ? 64 + tx * 4 : tx * 4);   // 4 consecutive cols, same head
            int h = colb >> 6, d = colb & 63;
            float4 o;
            o.x = (acc[i][jj * 4 + 0] + bias[colb + 0]) * scale;
            o.y = (acc[i][jj * 4 + 1] + bias[colb + 1]) * scale;
            o.z = (acc[i][jj * 4 + 2] + bias[colb + 2]) * scale;
            o.w = (acc[i][jj * 4 + 3] + bias[colb + 3]) * scale;
            *(float4*)(outp + (size_t)((h * BB + bidx) * LL + l) * DKK + d) = o;
        }
    }
}

// =====================================================================
// Kernel 2a: scores S = (Q/64) @ K^T with mask, per (h,b), 128x128 tile
// =====================================================================
__global__ __launch_bounds__(256) void scores_kernel(
    const int* __restrict__ mask, float* __restrict__ attn)
{
    __shared__ float As[16][128];   // [d][qrow]
    __shared__ float Bs[16][128];   // [d][krow]

    const int hb = blockIdx.z;
    const int q0 = blockIdx.y * 128;
    const int k0 = blockIdx.x * 128;
    const int b  = hb & 1;
    const float* qh = g_qh + (size_t)hb * LL * DKK;
    const float* kh = g_kh + (size_t)hb * LL * DKK;
    const int t = threadIdx.x, tx = t & 15, ty = t >> 4;

    float acc[8][8];
#pragma unroll
    for (int i = 0; i < 8; i++)
#pragma unroll
        for (int j = 0; j < 8; j++) acc[i][j] = 0.0f;

    for (int d0 = 0; d0 < DKK; d0 += 16) {
#pragma unroll
        for (int p = 0; p < 2; p++) {
            int fi = t + p * 256;
            int d4 = fi & 3, row = fi >> 2;
            float4 fa = *(const float4*)(qh + (size_t)(q0 + row) * DKK + d0 + d4 * 4);
            As[d4 * 4 + 0][row] = fa.x; As[d4 * 4 + 1][row] = fa.y;
            As[d4 * 4 + 2][row] = fa.z; As[d4 * 4 + 3][row] = fa.w;
            float4 fb = *(const float4*)(kh + (size_t)(k0 + row) * DKK + d0 + d4 * 4);
            Bs[d4 * 4 + 0][row] = fb.x; Bs[d4 * 4 + 1][row] = fb.y;
            Bs[d4 * 4 + 2][row] = fb.z; Bs[d4 * 4 + 3][row] = fb.w;
        }
        __syncthreads();
#pragma unroll
        for (int dd = 0; dd < 16; dd++) {
            float a[8], bf[8];
            *(float4*)&a[0]  = *(float4*)&As[dd][ty * 4];
            *(float4*)&a[4]  = *(float4*)&As[dd][64 + ty * 4];
            *(float4*)&bf[0] = *(float4*)&Bs[dd][tx * 4];
            *(float4*)&bf[4] = *(float4*)&Bs[dd][64 + tx * 4];
#pragma unroll
            for (int i = 0; i < 8; i++)
#pragma unroll
                for (int j = 0; j < 8; j++) acc[i][j] += a[i] * bf[j];
        }
        __syncthreads();
    }

    float* ab = attn + (size_t)hb * LL * LL;
    const int* mb = mask + (size_t)b * LL * LL;
#pragma unroll
    for (int i = 0; i < 8; i++) {
        int r = q0 + ((i < 4) ? ty * 4 + i : 64 + ty * 4 + (i - 4));
#pragma unroll
        for (int jj = 0; jj < 2; jj++) {
            int cb = k0 + (jj ? 64 + tx * 4 : tx * 4);
            int4 mv = *(const int4*)(mb + (size_t)r * LL + cb);
            float4 o;
            o.x = mv.x ? acc[i][jj * 4 + 0] : -1e9f;
            o.y = mv.y ? acc[i][jj * 4 + 1] : -1e9f;
            o.z = mv.z ? acc[i][jj * 4 + 2] : -1e9f;
            o.w = mv.w ? acc[i][jj * 4 + 3] : -1e9f;
            *(float4*)(ab + (size_t)r * LL + cb) = o;
        }
    }
}

// =====================================================================
// Kernel 2b: per-row max & 1/sumexp.  One block per row (32768 rows).
// =====================================================================
__global__ __launch_bounds__(256) void rowstats_kernel(const float* __restrict__ attn)
{
    const int r = blockIdx.x;
    const float4* row = (const float4*)(attn + (size_t)r * LL);
    const int t = threadIdx.x;

    float4 v0 = row[t];
    float4 v1 = row[t + 256];
    float mx = fmaxf(fmaxf(fmaxf(v0.x, v0.y), fmaxf(v0.z, v0.w)),
                     fmaxf(fmaxf(v1.x, v1.y), fmaxf(v1.z, v1.w)));
#pragma unroll
    for (int o = 16; o > 0; o >>= 1) mx = fmaxf(mx, __shfl_xor_sync(0xffffffffu, mx, o));

    __shared__ float sred[8];
    __shared__ float sbmax;
    int lane = t & 31, w = t >> 5;
    if (lane == 0) sred[w] = mx;
    __syncthreads();
    if (t == 0) {
        float m2 = sred[0];
#pragma unroll
        for (int i = 1; i < 8; i++) m2 = fmaxf(m2, sred[i]);
        sbmax = m2;
    }
    __syncthreads();
    mx = sbmax;

    float s = __expf(v0.x - mx) + __expf(v0.y - mx) + __expf(v0.z - mx) + __expf(v0.w - mx)
            + __expf(v1.x - mx) + __expf(v1.y - mx) + __expf(v1.z - mx) + __expf(v1.w - mx);
#pragma unroll
    for (int o = 16; o > 0; o >>= 1) s += __shfl_xor_sync(0xffffffffu, s, o);
    if (lane == 0) sred[w] = s;
    __syncthreads();
    if (t == 0) {
        float tot = 0.0f;
#pragma unroll
        for (int i = 0; i < 8; i++) tot += sred[i];
        g_m[r] = mx;
        g_linv[r] = 1.0f / tot;
    }
}

// =====================================================================
// Kernel 2c: P = exp(S-m)/l  (written back to attn output)  and ctx = P@V
// Block: q-tile of 128 rows for one (h,b).  K processed in chunks of 32.
// =====================================================================
__global__ __launch_bounds__(256) void pv_kernel(float* __restrict__ attn)
{
    __shared__ float Ps[32][132];   // [k][q], padded (132*4B = 528B, 16B-aligned rows)
    __shared__ float Vs[32][64];    // [k][d]

    const int hb = blockIdx.y;
    const int q0 = blockIdx.x * 128;
    const int t = threadIdx.x, tx = t & 15, ty = t >> 4;

    float* attnBase = attn + (size_t)hb * LL * LL + (size_t)q0 * LL;
    const float* vhBase = g_vh + (size_t)hb * LL * DKK;

    // each thread's transform rows are fixed across the k loop
    float mrow[4], lrow[4];
    const int myrow = t >> 3;
#pragma unroll
    for (int p = 0; p < 4; p++) {
        mrow[p] = g_m[hb * LL + q0 + myrow + p * 32];
        lrow[p] = g_linv[hb * LL + q0 + myrow + p * 32];
    }

    float acc[8][4];
#pragma unroll
    for (int i = 0; i < 8; i++)
#pragma unroll
        for (int j = 0; j < 4; j++) acc[i][j] = 0.0f;

    for (int k0 = 0; k0 < LL; k0 += 32) {
        // load 128x32 score tile, normalize, write P back, stage transposed
#pragma unroll
        for (int p = 0; p < 4; p++) {
            int fi = t + p * 256;
            int col4 = fi & 7, row = fi >> 3;
            float* gp = attnBase + (size_t)row * LL + k0 + col4 * 4;
            float4 sv = *(const float4*)gp;
            float m = mrow[p], li = lrow[p];
            float4 pv;
            pv.x = __expf(sv.x - m) * li;
            pv.y = __expf(sv.y - m) * li;
            pv.z = __expf(sv.z - m) * li;
            pv.w = __expf(sv.w - m) * li;
            *(float4*)gp = pv;
            int c = col4 * 4;
            Ps[c + 0][row] = pv.x; Ps[c + 1][row] = pv.y;
            Ps[c + 2][row] = pv.z; Ps[c + 3][row] = pv.w;
        }
        // load V chunk 32x64
#pragma unroll
        for (int p = 0; p < 2; p++) {
            int fi = t + p * 256;
            int d4 = fi & 15, kr = fi >> 4;
            float4 f = *(const float4*)(vhBase + (size_t)(k0 + kr) * DKK + d4 * 4);
            *(float4*)&Vs[kr][d4 * 4] = f;
        }
        __syncthreads();
#pragma unroll
        for (int kk = 0; kk < 32; kk++) {
            float a[8], bf[4];
            *(float4*)&a[0]  = *(float4*)&Ps[kk][ty * 4];
            *(float4*)&a[4]  = *(float4*)&Ps[kk][64 + ty * 4];
            *(float4*)&bf[0] = *(float4*)&Vs[kk][tx * 4];
#pragma unroll
            for (int i = 0; i < 8; i++)
#pragma unroll
                for (int j = 0; j < 4; j++) acc[i][j] += a[i] * bf[j];
        }
        __syncthreads();
    }

    // ctx: [b*L + l][h*64 + d]
    const int h = hb >> 1, b = hb & 1;
#pragma unroll
    for (int i = 0; i < 8; i++) {
        int row = q0 + ((i < 4) ? ty * 4 + i : 64 + ty * 4 + (i - 4));
        float4 o = {acc[i][0], acc[i][1], acc[i][2], acc[i][3]};
        *(float4*)(g_ctx + (size_t)(b * LL + row) * DMODEL + h * 64 + tx * 4) = o;
    }
}

// =====================================================================
// Kernel 3: out = ctx @ Wo + bo + residual(q)
// =====================================================================
__global__ __launch_bounds__(256) void outproj_kernel(
    const float* __restrict__ resid, const float* __restrict__ Wo,
    const float* __restrict__ bo, float* __restrict__ out)
{
    __shared__ float As[16][128];
    __shared__ float Bs[16][128];

    const int col0 = blockIdx.x * 128;
    const int row0 = blockIdx.y * 128;
    const int t = threadIdx.x, tx = t & 15, ty = t >> 4;

    float acc[8][8];
#pragma unroll
    for (int i = 0; i < 8; i++)
#pragma unroll
        for (int j = 0; j < 8; j++) acc[i][j] = 0.0f;

    for (int k0 = 0; k0 < DMODEL; k0 += 16) {
#pragma unroll
        for (int p = 0; p < 2; p++) {
            int fi = t + p * 256;
            int k4 = fi & 3, row = fi >> 2;
            float4 fa = *(const float4*)(g_ctx + (size_t)(row0 + row) * DMODEL + k0 + k4 * 4);
            As[k4 * 4 + 0][row] = fa.x; As[k4 * 4 + 1][row] = fa.y;
            As[k4 * 4 + 2][row] = fa.z; As[k4 * 4 + 3][row] = fa.w;
            int c4 = fi & 31, kk = fi >> 5;
            float4 fb = *(const float4*)(Wo + (size_t)(k0 + kk) * DMODEL + col0 + c4 * 4);
            *(float4*)&Bs[kk][c4 * 4] = fb;
        }
        __syncthreads();
#pragma unroll
        for (int kk = 0; kk < 16; kk++) {
            float a[8], bf[8];
            *(float4*)&a[0]  = *(float4*)&As[kk][ty * 4];
            *(float4*)&a[4]  = *(float4*)&As[kk][64 + ty * 4];
            *(float4*)&bf[0] = *(float4*)&Bs[kk][tx * 4];
            *(float4*)&bf[4] = *(float4*)&Bs[kk][64 + tx * 4];
#pragma unroll
            for (int i = 0; i < 8; i++)
#pragma unroll
                for (int j = 0; j < 8; j++) acc[i][j] += a[i] * bf[j];
        }
        __syncthreads();
    }

#pragma unroll
    for (int i = 0; i < 8; i++) {
        int row = row0 + ((i < 4) ? ty * 4 + i : 64 + ty * 4 + (i - 4));
#pragma unroll
        for (int jj = 0; jj < 2; jj++) {
            int cb = col0 + (jj ? 64 + tx * 4 : tx * 4);
            float4 rb = *(const float4*)(resid + (size_t)row * DMODEL + cb);
            float4 bb = *(const float4*)(bo + cb);
            float4 o;
            o.x = acc[i][jj * 4 + 0] + bb.x + rb.x;
            o.y = acc[i][jj * 4 + 1] + bb.y + rb.y;
            o.z = acc[i][jj * 4 + 2] + bb.z + rb.z;
            o.w = acc[i][jj * 4 + 3] + bb.w + rb.w;
            *(float4*)(out + (size_t)row * DMODEL + cb) = o;
        }
    }
}

// =====================================================================
extern "C" void kernel_launch(void* const* d_in, const int* in_sizes, int n_in,
                              void* d_out, int out_size)
{
    const float* q    = (const float*)d_in[0];
    const float* k    = (const float*)d_in[1];
    const float* v    = (const float*)d_in[2];
    const int*   mask = (const int*)  d_in[3];
    const float* Wq   = (const float*)d_in[4];
    const float* bq   = (const float*)d_in[5];
    const float* Wk   = (const float*)d_in[6];
    const float* bk   = (const float*)d_in[7];
    const float* Wv   = (const float*)d_in[8];
    const float* bv   = (const float*)d_in[9];
    const float* Wo   = (const float*)d_in[10];
    const float* bo   = (const float*)d_in[11];

    float* out  = (float*)d_out;
    float* attn = out + (size_t)NT * DMODEL;   // output = [out | attn] per reference return order

    proj_kernel<<<dim3(4, 32, 3), 256>>>(q, k, v, Wq, bq, Wk, bk, Wv, bv);
    scores_kernel<<<dim3(16, 16, 16), 256>>>(mask, attn);
    rowstats_kernel<<<HB * LL, 256>>>(attn);
    pv_kernel<<<dim3(16, 16), 256>>>(attn);
    outproj_kernel<<<dim3(4, 32), 256>>>(q, Wo, bo, out);
}

// round 3
// speedup vs baseline: 1.2832x; 1.2832x over previous
#include <cuda_runtime.h>

#define LL   2048
#define BB   2
#define DMODEL 512
#define HH   8
#define DKK  64
#define NT   4096   // BB*LL
#define HB   16     // HH*BB
#define KT   16     // k tiles of 128 in scores

// ---------------- scratch (device globals; no allocation allowed) ----------------
__device__ float g_qh[HB * LL * DKK];   // [h*2+b][l][d], pre-scaled by 1/64
__device__ float g_kh[HB * LL * DKK];
__device__ float g_vh[HB * LL * DKK];
__device__ float g_ctxa[NT * DMODEL];   // ctx partial, k-split 0
__device__ float g_ctxb[NT * DMODEL];   // ctx partial, k-split 1
__device__ float g_pmax[HB * LL * KT];  // per (row, ktile) max
__device__ float g_psum[HB * LL * KT];  // per (row, ktile) sumexp(rel to tile max)
__device__ float g_m[HB * LL];          // global row max
__device__ float g_linv[HB * LL];       // 1 / row sumexp

// ---------------- packed f32x2 helpers (sm_100+ FFMA2) ----------------
__device__ __forceinline__ unsigned long long pack2(float x) {
    unsigned long long r;
    asm("mov.b64 %0, {%1, %1};" : "=l"(r) : "f"(x));
    return r;
}
__device__ __forceinline__ void ffma2(unsigned long long& d, unsigned long long a, unsigned long long b) {
    asm("fma.rn.f32x2 %0, %1, %2, %0;" : "+l"(d) : "l"(a), "l"(b));
}
__device__ __forceinline__ float2 unpk(unsigned long long p) {
    float2 r;
    asm("mov.b64 {%0, %1}, %2;" : "=f"(r.x), "=f"(r.y) : "l"(p));
    return r;
}

// =====================================================================
// Kernel 1: fused QKV projection.  Y = (X @ W + b) [* 1/64 for Q]
// 128x128x16 tile, 256 threads, 8x8 microtile via FFMA2.
// =====================================================================
__global__ __launch_bounds__(256) void proj_kernel(
    const float* __restrict__ qin, const float* __restrict__ kin, const float* __restrict__ vin,
    const float* __restrict__ Wq, const float* __restrict__ bq,
    const float* __restrict__ Wk, const float* __restrict__ bk,
    const float* __restrict__ Wv, const float* __restrict__ bv)
{
    __shared__ float As[16][128];   // [k][row]
    __shared__ float Bs[16][128];   // [k][col]

    const int z = blockIdx.z;
    const float* X    = (z == 0) ? qin : (z == 1) ? kin : vin;
    const float* W    = (z == 0) ? Wq  : (z == 1) ? Wk  : Wv;
    const float* bias = (z == 0) ? bq  : (z == 1) ? bk  : bv;
    float* outp       = (z == 0) ? g_qh : (z == 1) ? g_kh : g_vh;
    const float scale = (z == 0) ? (1.0f / 64.0f) : 1.0f;

    const int col0 = blockIdx.x * 128;
    const int row0 = blockIdx.y * 128;
    const int t = threadIdx.x, tx = t & 15, ty = t >> 4;

    unsigned long long acc[8][4];
#pragma unroll
    for (int i = 0; i < 8; i++)
#pragma unroll
        for (int j = 0; j < 4; j++) acc[i][j] = 0ull;

    for (int k0 = 0; k0 < DMODEL; k0 += 16) {
#pragma unroll
        for (int p = 0; p < 2; p++) {
            int fi = t + p * 256;
            int k4 = fi & 3, row = fi >> 2;
            float4 fa = *(const float4*)(X + (size_t)(row0 + row) * DMODEL + k0 + k4 * 4);
            As[k4 * 4 + 0][row] = fa.x; As[k4 * 4 + 1][row] = fa.y;
            As[k4 * 4 + 2][row] = fa.z; As[k4 * 4 + 3][row] = fa.w;
            int c4 = fi & 31, kk = fi >> 5;
            float4 fb = *(const float4*)(W + (size_t)(k0 + kk) * DMODEL + col0 + c4 * 4);
            *(float4*)&Bs[kk][c4 * 4] = fb;
        }
        __syncthreads();
#pragma unroll
        for (int kk = 0; kk < 16; kk++) {
            float a[8];
            *(float4*)&a[0] = *(float4*)&As[kk][ty * 4];
            *(float4*)&a[4] = *(float4*)&As[kk][64 + ty * 4];
            ulonglong2 b0 = *(ulonglong2*)&Bs[kk][tx * 4];
            ulonglong2 b1 = *(ulonglong2*)&Bs[kk][64 + tx * 4];
            unsigned long long bp[4] = {b0.x, b0.y, b1.x, b1.y};
            unsigned long long ad[8];
#pragma unroll
            for (int i = 0; i < 8; i++) ad[i] = pack2(a[i]);
#pragma unroll
            for (int i = 0; i < 8; i++)
#pragma unroll
                for (int j = 0; j < 4; j++) ffma2(acc[i][j], ad[i], bp[j]);
        }
        __syncthreads();
    }

#pragma unroll
    for (int i = 0; i < 8; i++) {
        int row = row0 + ((i < 4) ? ty * 4 + i : 64 + ty * 4 + (i - 4));
        int bidx = row >> 11, l = row & 2047;
#pragma unroll
        for (int jj = 0; jj < 2; jj++) {
            int colb = col0 + (jj ? 64 + tx * 4 : tx * 4);
            int h = colb >> 6, d = colb & 63;
            float2 u0 = unpk(acc[i][jj * 2 + 0]);
            float2 u1 = unpk(acc[i][jj * 2 + 1]);
            float4 o;
            o.x = (u0.x + bias[colb + 0]) * scale;
            o.y = (u0.y + bias[colb + 1]) * scale;
            o.z = (u1.x + bias[colb + 2]) * scale;
            o.w = (u1.y + bias[colb + 3]) * scale;
            *(float4*)(outp + (size_t)((h * BB + bidx) * LL + l) * DKK + d) = o;
        }
    }
}

// =====================================================================
// Kernel 2a: S = (Q/64) @ K^T + mask, and per-(row, ktile) softmax stats.
// =====================================================================
__global__ __launch_bounds__(256) void scores_kernel(
    const int* __restrict__ mask, float* __restrict__ attn)
{
    __shared__ float As[16][128];   // [d][qrow]
    __shared__ float Bs[16][128];   // [d][krow]

    const int hb = blockIdx.z;
    const int q0 = blockIdx.y * 128;
    const int k0 = blockIdx.x * 128;
    const int kt = blockIdx.x;
    const int b  = hb & 1;
    const float* qh = g_qh + (size_t)hb * LL * DKK;
    const float* kh = g_kh + (size_t)hb * LL * DKK;
    const int t = threadIdx.x, tx = t & 15, ty = t >> 4;

    unsigned long long acc[8][4];
#pragma unroll
    for (int i = 0; i < 8; i++)
#pragma unroll
        for (int j = 0; j < 4; j++) acc[i][j] = 0ull;

    for (int d0 = 0; d0 < DKK; d0 += 16) {
#pragma unroll
        for (int p = 0; p < 2; p++) {
            int fi = t + p * 256;
            int d4 = fi & 3, row = fi >> 2;
            float4 fa = *(const float4*)(qh + (size_t)(q0 + row) * DKK + d0 + d4 * 4);
            As[d4 * 4 + 0][row] = fa.x; As[d4 * 4 + 1][row] = fa.y;
            As[d4 * 4 + 2][row] = fa.z; As[d4 * 4 + 3][row] = fa.w;
            float4 fb = *(const float4*)(kh + (size_t)(k0 + row) * DKK + d0 + d4 * 4);
            Bs[d4 * 4 + 0][row] = fb.x; Bs[d4 * 4 + 1][row] = fb.y;
            Bs[d4 * 4 + 2][row] = fb.z; Bs[d4 * 4 + 3][row] = fb.w;
        }
        __syncthreads();
#pragma unroll
        for (int dd = 0; dd < 16; dd++) {
            float a[8];
            *(float4*)&a[0] = *(float4*)&As[dd][ty * 4];
            *(float4*)&a[4] = *(float4*)&As[dd][64 + ty * 4];
            ulonglong2 b0 = *(ulonglong2*)&Bs[dd][tx * 4];
            ulonglong2 b1 = *(ulonglong2*)&Bs[dd][64 + tx * 4];
            unsigned long long bp[4] = {b0.x, b0.y, b1.x, b1.y};
            unsigned long long ad[8];
#pragma unroll
            for (int i = 0; i < 8; i++) ad[i] = pack2(a[i]);
#pragma unroll
            for (int i = 0; i < 8; i++)
#pragma unroll
                for (int j = 0; j < 4; j++) ffma2(acc[i][j], ad[i], bp[j]);
        }
        __syncthreads();
    }

    float* ab = attn + (size_t)hb * LL * LL;
    const int* mb = mask + (size_t)b * LL * LL;
#pragma unroll
    for (int i = 0; i < 8; i++) {
        int r = q0 + ((i < 4) ? ty * 4 + i : 64 + ty * 4 + (i - 4));
        float c[8];
#pragma unroll
        for (int jj = 0; jj < 2; jj++) {
            int cb = k0 + (jj ? 64 + tx * 4 : tx * 4);
            int4 mv = *(const int4*)(mb + (size_t)r * LL + cb);
            float2 u0 = unpk(acc[i][jj * 2 + 0]);
            float2 u1 = unpk(acc[i][jj * 2 + 1]);
            float4 o;
            o.x = mv.x ? u0.x : -1e9f;
            o.y = mv.y ? u0.y : -1e9f;
            o.z = mv.z ? u1.x : -1e9f;
            o.w = mv.w ? u1.y : -1e9f;
            *(float4*)(ab + (size_t)r * LL + cb) = o;
            c[jj * 4 + 0] = o.x; c[jj * 4 + 1] = o.y;
            c[jj * 4 + 2] = o.z; c[jj * 4 + 3] = o.w;
        }
        // per-thread (max, sumexp) over its 8 cols of this row
        float mx = c[0];
#pragma unroll
        for (int j = 1; j < 8; j++) mx = fmaxf(mx, c[j]);
        float ss = 0.0f;
#pragma unroll
        for (int j = 0; j < 8; j++) ss += __expf(c[j] - mx);
        // merge across the 16 threads sharing this row (offsets stay in 16-group)
#pragma unroll
        for (int o = 1; o < 16; o <<= 1) {
            float mo = __shfl_xor_sync(0xffffffffu, mx, o);
            float so = __shfl_xor_sync(0xffffffffu, ss, o);
            float mn = fmaxf(mx, mo);
            ss = ss * __expf(mx - mn) + so * __expf(mo - mn);
            mx = mn;
        }
        if (tx == 0) {
            g_pmax[(size_t)(hb * LL + r) * KT + kt] = mx;
            g_psum[(size_t)(hb * LL + r) * KT + kt] = ss;
        }
    }
}

// =====================================================================
// Kernel 2b: combine per-tile stats -> global row max + 1/sumexp
// =====================================================================
__global__ __launch_bounds__(256) void combine_kernel()
{
    int r = blockIdx.x * 256 + threadIdx.x;   // 32768 rows
    float M = -3.4e38f;
#pragma unroll
    for (int j = 0; j < KT; j++) M = fmaxf(M, g_pmax[(size_t)r * KT + j]);
    float L = 0.0f;
#pragma unroll
    for (int j = 0; j < KT; j++)
        L += g_psum[(size_t)r * KT + j] * __expf(g_pmax[(size_t)r * KT + j] - M);
    g_m[r] = M;
    g_linv[r] = 1.0f / L;
}

// =====================================================================
// Kernel 2c: P = exp(S-m)/l (written back) and ctx_part = P@V over k-split.
// Block: 64 q rows x 64 d cols, k chunk 64, grid (32, 16, 2).
// =====================================================================
__global__ __launch_bounds__(256) void pv_kernel(float* __restrict__ attn)
{
    __shared__ float Ps[64][68];   // [k][q]
    __shared__ float Vs[64][68];   // [k][d]

    const int hb = blockIdx.y;
    const int q0 = blockIdx.x * 64;
    const int ks = blockIdx.z;
    const int t = threadIdx.x, tx = t & 15, ty = t >> 4;

    float* attnBase = attn + (size_t)hb * LL * LL + (size_t)q0 * LL;
    const float* vhBase = g_vh + (size_t)hb * LL * DKK;
    float* ctxp = ks ? g_ctxb : g_ctxa;

    float mrow[4], lrow[4];
#pragma unroll
    for (int p = 0; p < 4; p++) {
        mrow[p] = g_m[hb * LL + q0 + ty + p * 16];
        lrow[p] = g_linv[hb * LL + q0 + ty + p * 16];
    }

    unsigned long long acc[4][2];
#pragma unroll
    for (int i = 0; i < 4; i++) { acc[i][0] = 0ull; acc[i][1] = 0ull; }

    const int kbeg = ks * (LL / 2);
    const int kend = kbeg + (LL / 2);
    for (int k0 = kbeg; k0 < kend; k0 += 64) {
        // stage 64x64 S tile -> P (write back) -> Ps transposed
#pragma unroll
        for (int p = 0; p < 4; p++) {
            int row = ty + p * 16;
            float* gp = attnBase + (size_t)row * LL + k0 + tx * 4;
            float4 sv = *(const float4*)gp;
            float m = mrow[p], li = lrow[p];
            float4 pvv;
            pvv.x = __expf(sv.x - m) * li;
            pvv.y = __expf(sv.y - m) * li;
            pvv.z = __expf(sv.z - m) * li;
            pvv.w = __expf(sv.w - m) * li;
            *(float4*)gp = pvv;
            int c = tx * 4;
            Ps[c + 0][row] = pvv.x; Ps[c + 1][row] = pvv.y;
            Ps[c + 2][row] = pvv.z; Ps[c + 3][row] = pvv.w;
        }
        // stage V 64x64
#pragma unroll
        for (int p = 0; p < 4; p++) {
            int kr = ty + p * 16;
            float4 f = *(const float4*)(vhBase + (size_t)(k0 + kr) * DKK + tx * 4);
            *(float4*)&Vs[kr][tx * 4] = f;
        }
        __syncthreads();
#pragma unroll
        for (int kk = 0; kk < 64; kk++) {
            float a[4];
            *(float4*)&a[0] = *(float4*)&Ps[kk][ty * 4];
            ulonglong2 bb = *(ulonglong2*)&Vs[kk][tx * 4];
            unsigned long long bp[2] = {bb.x, bb.y};
            unsigned long long ad[4];
#pragma unroll
            for (int i = 0; i < 4; i++) ad[i] = pack2(a[i]);
#pragma unroll
            for (int i = 0; i < 4; i++) {
                ffma2(acc[i][0], ad[i], bp[0]);
                ffma2(acc[i][1], ad[i], bp[1]);
            }
        }
        __syncthreads();
    }

    const int h = hb >> 1, b = hb & 1;
#pragma unroll
    for (int i = 0; i < 4; i++) {
        int row = q0 + ty * 4 + i;
        float2 u0 = unpk(acc[i][0]);
        float2 u1 = unpk(acc[i][1]);
        float4 o = {u0.x, u0.y, u1.x, u1.y};
        *(float4*)(ctxp + (size_t)(b * LL + row) * DMODEL + h * 64 + tx * 4) = o;
    }
}

// =====================================================================
// Kernel 3: out = (ctxa + ctxb) @ Wo + bo + residual(q)
// =====================================================================
__global__ __launch_bounds__(256) void outproj_kernel(
    const float* __restrict__ resid, const float* __restrict__ Wo,
    const float* __restrict__ bo, float* __restrict__ out)
{
    __shared__ float As[16][128];
    __shared__ float Bs[16][128];

    const int col0 = blockIdx.x * 128;
    const int row0 = blockIdx.y * 128;
    const int t = threadIdx.x, tx = t & 15, ty = t >> 4;

    unsigned long long acc[8][4];
#pragma unroll
    for (int i = 0; i < 8; i++)
#pragma unroll
        for (int j = 0; j < 4; j++) acc[i][j] = 0ull;

    for (int k0 = 0; k0 < DMODEL; k0 += 16) {
#pragma unroll
        for (int p = 0; p < 2; p++) {
            int fi = t + p * 256;
            int k4 = fi & 3, row = fi >> 2;
            size_t ia = (size_t)(row0 + row) * DMODEL + k0 + k4 * 4;
            float4 fa = *(const float4*)(g_ctxa + ia);
            float4 f2 = *(const float4*)(g_ctxb + ia);
            As[k4 * 4 + 0][row] = fa.x + f2.x; As[k4 * 4 + 1][row] = fa.y + f2.y;
            As[k4 * 4 + 2][row] = fa.z + f2.z; As[k4 * 4 + 3][row] = fa.w + f2.w;
            int c4 = fi & 31, kk = fi >> 5;
            float4 fb = *(const float4*)(Wo + (size_t)(k0 + kk) * DMODEL + col0 + c4 * 4);
            *(float4*)&Bs[kk][c4 * 4] = fb;
        }
        __syncthreads();
#pragma unroll
        for (int kk = 0; kk < 16; kk++) {
            float a[8];
            *(float4*)&a[0] = *(float4*)&As[kk][ty * 4];
            *(float4*)&a[4] = *(float4*)&As[kk][64 + ty * 4];
            ulonglong2 b0 = *(ulonglong2*)&Bs[kk][tx * 4];
            ulonglong2 b1 = *(ulonglong2*)&Bs[kk][64 + tx * 4];
            unsigned long long bp[4] = {b0.x, b0.y, b1.x, b1.y};
            unsigned long long ad[8];
#pragma unroll
            for (int i = 0; i < 8; i++) ad[i] = pack2(a[i]);
#pragma unroll
            for (int i = 0; i < 8; i++)
#pragma unroll
                for (int j = 0; j < 4; j++) ffma2(acc[i][j], ad[i], bp[j]);
        }
        __syncthreads();
    }

#pragma unroll
    for (int i = 0; i < 8; i++) {
        int row = row0 + ((i < 4) ? ty * 4 + i : 64 + ty * 4 + (i - 4));
#pragma unroll
        for (int jj = 0; jj < 2; jj++) {
            int cb = col0 + (jj ? 64 + tx * 4 : tx * 4);
            float4 rb = *(const float4*)(resid + (size_t)row * DMODEL + cb);
            float4 bb = *(const float4*)(bo + cb);
            float2 u0 = unpk(acc[i][jj * 2 + 0]);
            float2 u1 = unpk(acc[i][jj * 2 + 1]);
            float4 o;
            o.x = u0.x + bb.x + rb.x;
            o.y = u0.y + bb.y + rb.y;
            o.z = u1.x + bb.z + rb.z;
            o.w = u1.y + bb.w + rb.w;
            *(float4*)(out + (size_t)row * DMODEL + cb) = o;
        }
    }
}

// =====================================================================
extern "C" void kernel_launch(void* const* d_in, const int* in_sizes, int n_in,
                              void* d_out, int out_size)
{
    const float* q    = (const float*)d_in[0];
    const float* k    = (const float*)d_in[1];
    const float* v    = (const float*)d_in[2];
    const int*   mask = (const int*)  d_in[3];
    const float* Wq   = (const float*)d_in[4];
    const float* bq   = (const float*)d_in[5];
    const float* Wk   = (const float*)d_in[6];
    const float* bk   = (const float*)d_in[7];
    const float* Wv   = (const float*)d_in[8];
    const float* bv   = (const float*)d_in[9];
    const float* Wo   = (const float*)d_in[10];
    const float* bo   = (const float*)d_in[11];

    float* out  = (float*)d_out;
    float* attn = out + (size_t)NT * DMODEL;

    proj_kernel<<<dim3(4, 32, 3), 256>>>(q, k, v, Wq, bq, Wk, bk, Wv, bv);
    scores_kernel<<<dim3(16, 16, 16), 256>>>(mask, attn);
    combine_kernel<<<128, 256>>>();
    pv_kernel<<<dim3(32, 16, 2), 256>>>(attn);
    outproj_kernel<<<dim3(4, 32), 256>>>(q, Wo, bo, out);
}